// round 1
// baseline (speedup 1.0000x reference)
#include <cuda_runtime.h>
#include <math_constants.h>

#define NB      16      // batches
#define NPTS    4096    // points per cloud (both sides)
#define TILE    1024    // ref points cached in smem per iteration
#define THREADS 128     // threads per block, 1 query per thread
#define BLOCKS_PER_BATCH (NPTS / THREADS)          // 32
#define BLOCKS_PER_PASS  (NB * BLOCKS_PER_BATCH)   // 512

// Scratch (no cudaMalloc allowed): packed points {x,y,z,||p||^2} and partial sums.
__device__ float4 g_pack[2][NB * NPTS];
__device__ float  g_partials[2 * BLOCKS_PER_PASS];

__global__ void pack_kernel(const float* __restrict__ p1,
                            const float* __restrict__ p2) {
    int i = blockIdx.x * blockDim.x + threadIdx.x;
    if (i >= NB * NPTS) return;
    float x = p1[3 * i + 0], y = p1[3 * i + 1], z = p1[3 * i + 2];
    g_pack[0][i] = make_float4(x, y, z, fmaf(x, x, fmaf(y, y, z * z)));
    x = p2[3 * i + 0]; y = p2[3 * i + 1]; z = p2[3 * i + 2];
    g_pack[1][i] = make_float4(x, y, z, fmaf(x, x, fmaf(y, y, z * z)));
}

// One directed chamfer pass: for each query point, min squared distance to all
// refs in the same batch; block-sum of the mins goes to g_partials.
// dir==0: queries = pack[0] (points1), refs = pack[1] (points2)
// dir==1: queries = pack[1],           refs = pack[0]
__global__ void __launch_bounds__(THREADS)
chamfer_pass_kernel(int dir) {
    __shared__ float4 tile[TILE];
    __shared__ float  ssum[THREADS / 32];

    const float4* __restrict__ q = g_pack[dir];
    const float4* __restrict__ r = g_pack[dir ^ 1];

    const int b  = blockIdx.y;
    const int qi = b * NPTS + blockIdx.x * THREADS + threadIdx.x;

    const float4 qp  = q[qi];
    const float  m2x = -2.0f * qp.x;
    const float  m2y = -2.0f * qp.y;
    const float  m2z = -2.0f * qp.z;

    float acc0 = CUDART_INF_F, acc1 = CUDART_INF_F;
    float acc2 = CUDART_INF_F, acc3 = CUDART_INF_F;

    const float4* __restrict__ rb = r + b * NPTS;

    for (int t = 0; t < NPTS; t += TILE) {
        // Cooperative fill: coalesced LDG.128, conflict-free STS.128.
        #pragma unroll
        for (int j = threadIdx.x; j < TILE; j += THREADS)
            tile[j] = rb[t + j];
        __syncthreads();

        // Hot loop: per point = 3 FFMA + 1 FMNMX + 1 broadcast LDS.128.
        // 4 accumulators break the fmin dependency chain.
        #pragma unroll 8
        for (int j = 0; j < TILE; j += 4) {
            float4 p0 = tile[j + 0];
            float4 p1 = tile[j + 1];
            float4 p2 = tile[j + 2];
            float4 p3 = tile[j + 3];
            acc0 = fminf(acc0, fmaf(m2x, p0.x, fmaf(m2y, p0.y, fmaf(m2z, p0.z, p0.w))));
            acc1 = fminf(acc1, fmaf(m2x, p1.x, fmaf(m2y, p1.y, fmaf(m2z, p1.z, p1.w))));
            acc2 = fminf(acc2, fmaf(m2x, p2.x, fmaf(m2y, p2.y, fmaf(m2z, p2.z, p2.w))));
            acc3 = fminf(acc3, fmaf(m2x, p3.x, fmaf(m2y, p3.y, fmaf(m2z, p3.z, p3.w))));
        }
        __syncthreads();
    }

    // min distance for this query (add back ||q||^2)
    float best = fminf(fminf(acc0, acc1), fminf(acc2, acc3)) + qp.w;

    // Deterministic block reduction (no float atomics anywhere).
    #pragma unroll
    for (int o = 16; o > 0; o >>= 1)
        best += __shfl_down_sync(0xFFFFFFFFu, best, o);
    if ((threadIdx.x & 31) == 0) ssum[threadIdx.x >> 5] = best;
    __syncthreads();
    if (threadIdx.x == 0) {
        float s = 0.0f;
        #pragma unroll
        for (int w = 0; w < THREADS / 32; w++) s += ssum[w];
        g_partials[dir * BLOCKS_PER_PASS + blockIdx.y * gridDim.x + blockIdx.x] = s;
    }
}

__global__ void reduce_kernel(float* __restrict__ out) {
    __shared__ float ssum[8];
    const int total = 2 * BLOCKS_PER_PASS;  // 1024
    float v = 0.0f;
    for (int i = threadIdx.x; i < total; i += blockDim.x)
        v += g_partials[i];
    #pragma unroll
    for (int o = 16; o > 0; o >>= 1)
        v += __shfl_down_sync(0xFFFFFFFFu, v, o);
    if ((threadIdx.x & 31) == 0) ssum[threadIdx.x >> 5] = v;
    __syncthreads();
    if (threadIdx.x == 0) {
        float s = 0.0f;
        #pragma unroll
        for (int w = 0; w < 8; w++) s += ssum[w];
        out[0] = s * (1.0f / (float)NB);
    }
}

extern "C" void kernel_launch(void* const* d_in, const int* in_sizes, int n_in,
                              void* d_out, int out_size) {
    const float* p1 = (const float*)d_in[0];
    const float* p2 = (const float*)d_in[1];
    float* out = (float*)d_out;

    pack_kernel<<<(NB * NPTS + 255) / 256, 256>>>(p1, p2);

    dim3 grid(BLOCKS_PER_BATCH, NB);
    chamfer_pass_kernel<<<grid, THREADS>>>(0);
    chamfer_pass_kernel<<<grid, THREADS>>>(1);

    reduce_kernel<<<1, 256>>>(out);
}

// round 2
// speedup vs baseline: 1.4805x; 1.4805x over previous
#include <cuda_runtime.h>
#include <math_constants.h>

#define NB      16
#define NPTS    4096
#define NPAIRS  (NPTS / 2)          // 2048 point-pairs per cloud per batch
#define TILE_PAIRS 512              // pairs per smem tile = 16KB
#define THREADS 64
#define QPT     2                   // queries per thread
#define QPB     (THREADS * QPT)     // 128 queries per block
#define BPB     (NPTS / QPB)        // 32 blocks per batch per direction
#define BLOCKS_PER_PASS (NB * BPB)  // 512 per direction, 1024 total

typedef unsigned long long u64;

__device__ __forceinline__ u64 fma2(u64 a, u64 b, u64 c) {
    u64 d;
    asm("fma.rn.f32x2 %0, %1, %2, %3;" : "=l"(d) : "l"(a), "l"(b), "l"(c));
    return d;
}
__device__ __forceinline__ u64 pack2(float lo, float hi) {
    u64 d;
    asm("mov.b64 %0, {%1, %2};" : "=l"(d) : "f"(lo), "f"(hi));
    return d;
}
__device__ __forceinline__ void unpack2(u64 v, float& lo, float& hi) {
    asm("mov.b64 {%0, %1}, %2;" : "=f"(lo), "=f"(hi) : "l"(v));
}

// Scratch (no cudaMalloc allowed).
// g_pack: pair-packed SoA-of-pairs layout. For pair p (points 2p, 2p+1):
//   g_pack[side][2p]   = {x0, x1, y0, y1}
//   g_pack[side][2p+1] = {z0, z1, w0, w1}   (w = ||p||^2)
// g_q: plain per-point {x,y,z,||p||^2} for query-side access.
__device__ float4 g_pack[2][NB * NPTS];
__device__ float4 g_q[2][NB * NPTS];
__device__ float  g_partials[2 * BLOCKS_PER_PASS];

__global__ void pack_kernel(const float* __restrict__ p1,
                            const float* __restrict__ p2) {
    int i = blockIdx.x * blockDim.x + threadIdx.x;   // pair index
    if (i >= NB * NPAIRS) return;
    const float* src[2] = {p1, p2};
    #pragma unroll
    for (int s = 0; s < 2; s++) {
        const float* p = src[s] + 6 * i;
        float x0 = p[0], y0 = p[1], z0 = p[2];
        float x1 = p[3], y1 = p[4], z1 = p[5];
        float w0 = fmaf(x0, x0, fmaf(y0, y0, z0 * z0));
        float w1 = fmaf(x1, x1, fmaf(y1, y1, z1 * z1));
        g_pack[s][2 * i + 0] = make_float4(x0, x1, y0, y1);
        g_pack[s][2 * i + 1] = make_float4(z0, z1, w0, w1);
        g_q[s][2 * i + 0] = make_float4(x0, y0, z0, w0);
        g_q[s][2 * i + 1] = make_float4(x1, y1, z1, w1);
    }
}

// Fused bidirectional chamfer pass. blockIdx.z = direction.
// Each thread owns QPT=2 queries; each iteration consumes one packed
// point-pair (2 ref points) via 2 broadcast LDS.128, computes 4 pair
// distances with 6 FFMA2 (fma.rn.f32x2) + 4 scalar FMNMX.
__global__ void __launch_bounds__(THREADS)
chamfer_kernel() {
    __shared__ float4 tile[2 * TILE_PAIRS];   // 16 KB
    __shared__ float  ssum[THREADS / 32];

    const int dir = blockIdx.z;
    const int b   = blockIdx.y;
    const float4* __restrict__ qarr = g_q[dir];
    const float4* __restrict__ rp   = g_pack[dir ^ 1] + b * NPTS;

    const int qbase = b * NPTS + blockIdx.x * QPB + threadIdx.x;
    const float4 qA = qarr[qbase];
    const float4 qB = qarr[qbase + THREADS];

    // Splat -2*q components into f32x2 registers (one-time).
    const u64 aX = pack2(-2.0f * qA.x, -2.0f * qA.x);
    const u64 aY = pack2(-2.0f * qA.y, -2.0f * qA.y);
    const u64 aZ = pack2(-2.0f * qA.z, -2.0f * qA.z);
    const u64 bX = pack2(-2.0f * qB.x, -2.0f * qB.x);
    const u64 bY = pack2(-2.0f * qB.y, -2.0f * qB.y);
    const u64 bZ = pack2(-2.0f * qB.z, -2.0f * qB.z);

    float accA0 = CUDART_INF_F, accA1 = CUDART_INF_F;
    float accB0 = CUDART_INF_F, accB1 = CUDART_INF_F;

    for (int t = 0; t < NPAIRS; t += TILE_PAIRS) {
        // Cooperative fill: coalesced LDG.128 -> STS.128 (raw byte copy,
        // pair-packed layout preserved).
        #pragma unroll
        for (int j = threadIdx.x; j < 2 * TILE_PAIRS; j += THREADS)
            tile[j] = rp[2 * t + j];
        __syncthreads();

        const ulonglong2* __restrict__ tp = (const ulonglong2*)tile;
        #pragma unroll 4
        for (int j = 0; j < TILE_PAIRS; j++) {
            ulonglong2 xy = tp[2 * j];       // .x = {x0,x1}, .y = {y0,y1}
            ulonglong2 zw = tp[2 * j + 1];   // .x = {z0,z1}, .y = {w0,w1}
            u64 dA = fma2(aX, xy.x, fma2(aY, xy.y, fma2(aZ, zw.x, zw.y)));
            u64 dB = fma2(bX, xy.x, fma2(bY, xy.y, fma2(bZ, zw.x, zw.y)));
            float l, h;
            unpack2(dA, l, h);
            accA0 = fminf(accA0, l); accA1 = fminf(accA1, h);
            unpack2(dB, l, h);
            accB0 = fminf(accB0, l); accB1 = fminf(accB1, h);
        }
        __syncthreads();
    }

    float best = (fminf(accA0, accA1) + qA.w) + (fminf(accB0, accB1) + qB.w);

    // Deterministic block reduction (no float atomics).
    #pragma unroll
    for (int o = 16; o > 0; o >>= 1)
        best += __shfl_down_sync(0xFFFFFFFFu, best, o);
    if ((threadIdx.x & 31) == 0) ssum[threadIdx.x >> 5] = best;
    __syncthreads();
    if (threadIdx.x == 0) {
        float s = ssum[0] + ssum[1];
        g_partials[dir * BLOCKS_PER_PASS + b * BPB + blockIdx.x] = s;
    }
}

__global__ void reduce_kernel(float* __restrict__ out) {
    __shared__ float ssum[8];
    const int total = 2 * BLOCKS_PER_PASS;  // 1024
    float v = 0.0f;
    for (int i = threadIdx.x; i < total; i += blockDim.x)
        v += g_partials[i];
    #pragma unroll
    for (int o = 16; o > 0; o >>= 1)
        v += __shfl_down_sync(0xFFFFFFFFu, v, o);
    if ((threadIdx.x & 31) == 0) ssum[threadIdx.x >> 5] = v;
    __syncthreads();
    if (threadIdx.x == 0) {
        float s = 0.0f;
        #pragma unroll
        for (int w = 0; w < 8; w++) s += ssum[w];
        out[0] = s * (1.0f / (float)NB);
    }
}

extern "C" void kernel_launch(void* const* d_in, const int* in_sizes, int n_in,
                              void* d_out, int out_size) {
    const float* p1 = (const float*)d_in[0];
    const float* p2 = (const float*)d_in[1];
    float* out = (float*)d_out;

    pack_kernel<<<(NB * NPAIRS + 127) / 128, 128>>>(p1, p2);

    dim3 grid(BPB, NB, 2);
    chamfer_kernel<<<grid, THREADS>>>();

    reduce_kernel<<<1, 256>>>(out);
}

// round 3
// speedup vs baseline: 1.7395x; 1.1750x over previous
#include <cuda_runtime.h>
#include <math_constants.h>

#define NB      16
#define NPTS    4096
#define NPAIRS  (NPTS / 2)            // 2048 ref point-pairs per batch
#define SPLITS  4
#define REFS_PB (NPTS / SPLITS)       // 1024 refs per block = one 16KB tile
#define RPAIRS_PB (REFS_PB / 2)       // 512 packed ref pairs per block
#define THREADS 64
#define QPT     4
#define QPB     (THREADS * QPT)       // 256 queries per block
#define QBLKS   (NPTS / QPB)          // 16
#define TQ      (2 * NB * NPTS)       // 131072 total queries (both directions)
#define CBLOCKS 256                   // combine-kernel blocks

typedef unsigned long long u64;

__device__ __forceinline__ u64 fma2(u64 a, u64 b, u64 c) {
    u64 d;
    asm("fma.rn.f32x2 %0, %1, %2, %3;" : "=l"(d) : "l"(a), "l"(b), "l"(c));
    return d;
}
union f2u { float2 f; u64 u; };
__device__ __forceinline__ u64 splat2(float v) { f2u t; t.f = make_float2(v, v); return t.u; }

// Scratch (no cudaMalloc allowed).
// g_pack: pair-packed refs. pair p -> [2p]={x0,x1,y0,y1}, [2p+1]={z0,z1,w0,w1}, w=||p||^2
// g_q:    per-point {x,y,z,w}; g_qw: dense ||p||^2
__device__ float4 g_pack[2][NB * NPTS];
__device__ float4 g_q[2][NB * NPTS];
__device__ float  g_qw[2 * NB * NPTS];
__device__ float  g_minpart[TQ * SPLITS];     // per-query per-split min (2 MB)
__device__ float  g_partials[CBLOCKS];

__global__ void pack_kernel(const float* __restrict__ p1,
                            const float* __restrict__ p2) {
    int i = blockIdx.x * blockDim.x + threadIdx.x;   // (side, pair) flattened
    if (i >= 2 * NB * NPAIRS) return;
    int s = i >> 15;                 // NB*NPAIRS = 32768
    int p = i & 32767;
    const float2* src = (const float2*)(s ? p2 : p1);
    float2 f0 = src[3 * p], f1 = src[3 * p + 1], f2 = src[3 * p + 2];
    float x0 = f0.x, y0 = f0.y, z0 = f1.x;
    float x1 = f1.y, y1 = f2.x, z1 = f2.y;
    float w0 = fmaf(x0, x0, fmaf(y0, y0, z0 * z0));
    float w1 = fmaf(x1, x1, fmaf(y1, y1, z1 * z1));
    g_pack[s][2 * p + 0] = make_float4(x0, x1, y0, y1);
    g_pack[s][2 * p + 1] = make_float4(z0, z1, w0, w1);
    g_q[s][2 * p + 0] = make_float4(x0, y0, z0, w0);
    g_q[s][2 * p + 1] = make_float4(x1, y1, z1, w1);
    g_qw[s * (NB * NPTS) + 2 * p + 0] = w0;
    g_qw[s * (NB * NPTS) + 2 * p + 1] = w1;
}

// grid = (QBLKS*SPLITS, NB, 2). Each block: 256 queries x 1024 refs (one tile).
// Writes per-query partial min (excluding ||q||^2) to g_minpart.
__global__ void __launch_bounds__(THREADS)
chamfer_kernel() {
    __shared__ float4 tile[2 * RPAIRS_PB];   // 16 KB

    const int dir   = blockIdx.z;
    const int b     = blockIdx.y;
    const int qblk  = blockIdx.x / SPLITS;
    const int split = blockIdx.x % SPLITS;

    const float4* __restrict__ rp = g_pack[dir ^ 1] + b * NPTS + split * REFS_PB;

    // Cooperative tile fill: 16 coalesced LDG.128 per thread.
    #pragma unroll
    for (int j = threadIdx.x; j < 2 * RPAIRS_PB; j += THREADS)
        tile[j] = rp[j];

    // Load 4 queries and splat -2*q components while the fill lands.
    const int qib = qblk * QPB + threadIdx.x;       // query index within batch
    const float4* __restrict__ qarr = g_q[dir] + b * NPTS;
    u64 sX[QPT], sY[QPT], sZ[QPT];
    #pragma unroll
    for (int k = 0; k < QPT; k++) {
        float4 q = qarr[qib + k * THREADS];
        sX[k] = splat2(-2.0f * q.x);
        sY[k] = splat2(-2.0f * q.y);
        sZ[k] = splat2(-2.0f * q.z);
    }
    float2 acc[QPT];
    #pragma unroll
    for (int k = 0; k < QPT; k++) acc[k] = make_float2(CUDART_INF_F, CUDART_INF_F);

    __syncthreads();

    // Hot loop: per ref-pair = 2 LDS.128 + 12 FFMA2 + 8 FMNMX for 8 pair-distances.
    const ulonglong2* __restrict__ tp = (const ulonglong2*)tile;
    #pragma unroll 4
    for (int j = 0; j < RPAIRS_PB; j++) {
        ulonglong2 xy = tp[2 * j];       // {x0,x1},{y0,y1}
        ulonglong2 zw = tp[2 * j + 1];   // {z0,z1},{w0,w1}
        #pragma unroll
        for (int k = 0; k < QPT; k++) {
            f2u d;
            d.u = fma2(sX[k], xy.x, fma2(sY[k], xy.y, fma2(sZ[k], zw.x, zw.y)));
            acc[k].x = fminf(acc[k].x, d.f.x);
            acc[k].y = fminf(acc[k].y, d.f.y);
        }
    }

    // Write partial mins: g_minpart[((dir*NB+b)*NPTS + q) * SPLITS + split]
    float* mp = g_minpart + ((dir * NB + b) * NPTS) * SPLITS + split;
    #pragma unroll
    for (int k = 0; k < QPT; k++)
        mp[(qib + k * THREADS) * SPLITS] = fminf(acc[k].x, acc[k].y);
}

// Combine splits -> per-query min, add ||q||^2, block-sum (deterministic).
__global__ void __launch_bounds__(256)
combine_kernel() {
    __shared__ float ssum[8];
    float v = 0.0f;
    #pragma unroll
    for (int r = 0; r < 2; r++) {
        int g = blockIdx.x * 512 + r * 256 + threadIdx.x;  // flattened query id
        float4 m = ((const float4*)g_minpart)[g];
        float mn = fminf(fminf(m.x, m.y), fminf(m.z, m.w));
        v += mn + g_qw[g];
    }
    #pragma unroll
    for (int o = 16; o > 0; o >>= 1)
        v += __shfl_down_sync(0xFFFFFFFFu, v, o);
    if ((threadIdx.x & 31) == 0) ssum[threadIdx.x >> 5] = v;
    __syncthreads();
    if (threadIdx.x == 0) {
        float s = 0.0f;
        #pragma unroll
        for (int w = 0; w < 8; w++) s += ssum[w];
        g_partials[blockIdx.x] = s;
    }
}

__global__ void reduce_kernel(float* __restrict__ out) {
    __shared__ float ssum[8];
    float v = (threadIdx.x < CBLOCKS) ? g_partials[threadIdx.x] : 0.0f;
    #pragma unroll
    for (int o = 16; o > 0; o >>= 1)
        v += __shfl_down_sync(0xFFFFFFFFu, v, o);
    if ((threadIdx.x & 31) == 0) ssum[threadIdx.x >> 5] = v;
    __syncthreads();
    if (threadIdx.x == 0) {
        float s = 0.0f;
        #pragma unroll
        for (int w = 0; w < 8; w++) s += ssum[w];
        out[0] = s * (1.0f / (float)NB);
    }
}

extern "C" void kernel_launch(void* const* d_in, const int* in_sizes, int n_in,
                              void* d_out, int out_size) {
    const float* p1 = (const float*)d_in[0];
    const float* p2 = (const float*)d_in[1];
    float* out = (float*)d_out;

    pack_kernel<<<(2 * NB * NPAIRS + 255) / 256, 256>>>(p1, p2);

    dim3 grid(QBLKS * SPLITS, NB, 2);   // 64 x 16 x 2 = 2048 blocks
    chamfer_kernel<<<grid, THREADS>>>();

    combine_kernel<<<CBLOCKS, 256>>>();
    reduce_kernel<<<1, 256>>>(out);
}